// round 1
// baseline (speedup 1.0000x reference)
#include <cuda_runtime.h>

#define N_NODES 10000
#define N_EDGES 640000
#define FDIM 128
#define HDIM 128

#define BE 64           // edges (or nodes) per block tile
#define THREADS 512
#define IN_STRIDE 264   // padded stride for 257-wide input tile (mult of 4)
#define HID_STRIDE 132  // padded stride for 128-wide tiles (mult of 4)

// Scratch (device globals: no allocation allowed)
__device__ float g_hagg[N_NODES * HDIM];
__device__ float g_cagg[N_NODES * 3];
__device__ float g_cnt[N_NODES];

__device__ __forceinline__ float silu_f(float x) {
    return x / (1.0f + __expf(-x));
}

// Tiled GEMM: sOut[64][128] = act(sIn[64][K] @ W[K][128] + bias)
// Thread layout: tx = lane (4 output cols = tx*4..tx*4+3), ty = warp (4 rows = ty*4..ty*4+3)
// s_w: staging buffer, 16 rows x 33 float4 (= 2112 floats)
template<int K, bool SILU>
__device__ __forceinline__ void gemm_tile(
    const float* __restrict__ sIn, int inStride,
    const float* __restrict__ W, const float* __restrict__ bias,
    float* __restrict__ sOut, int outStride,
    float* __restrict__ s_w)
{
    const int tx = threadIdx.x & 31;
    const int ty = threadIdx.x >> 5;   // 0..15
    const int e0 = ty * 4;

    float acc[4][4];
#pragma unroll
    for (int i = 0; i < 4; i++)
#pragma unroll
        for (int c = 0; c < 4; c++) acc[i][c] = 0.0f;

    constexpr int KFULL = (K / 16) * 16;

    for (int kc = 0; kc < KFULL; kc += 16) {
        __syncthreads();   // protect s_w reuse
        {
            // 16 rows x 32 float4 = 512 loads; one per thread
            int t = threadIdx.x;
            int r = t >> 5, c = t & 31;
            ((float4*)s_w)[r * 33 + c] =
                *((const float4*)(W + (size_t)(kc + r) * 128) + c);
        }
        __syncthreads();
#pragma unroll
        for (int kk = 0; kk < 16; kk += 4) {
            float4 av[4];
#pragma unroll
            for (int i = 0; i < 4; i++)
                av[i] = *(const float4*)&sIn[(e0 + i) * inStride + kc + kk];
#pragma unroll
            for (int q = 0; q < 4; q++) {
                float4 w = ((const float4*)s_w)[(kk + q) * 33 + tx];
#pragma unroll
                for (int i = 0; i < 4; i++) {
                    float a = (q == 0) ? av[i].x : (q == 1) ? av[i].y
                              : (q == 2) ? av[i].z : av[i].w;
                    acc[i][0] = fmaf(a, w.x, acc[i][0]);
                    acc[i][1] = fmaf(a, w.y, acc[i][1]);
                    acc[i][2] = fmaf(a, w.z, acc[i][2]);
                    acc[i][3] = fmaf(a, w.w, acc[i][3]);
                }
            }
        }
    }

    if (K > KFULL) {  // tail rows (K=257 -> 1 row)
        constexpr int REM = K - KFULL;
        __syncthreads();
        if (threadIdx.x < REM * 32) {
            int t = threadIdx.x;
            int r = t >> 5, c = t & 31;
            ((float4*)s_w)[r * 33 + c] =
                *((const float4*)(W + (size_t)(KFULL + r) * 128) + c);
        }
        __syncthreads();
#pragma unroll
        for (int kk = 0; kk < REM; kk++) {
            float4 w = ((const float4*)s_w)[kk * 33 + tx];
#pragma unroll
            for (int i = 0; i < 4; i++) {
                float a = sIn[(e0 + i) * inStride + KFULL + kk];
                acc[i][0] = fmaf(a, w.x, acc[i][0]);
                acc[i][1] = fmaf(a, w.y, acc[i][1]);
                acc[i][2] = fmaf(a, w.z, acc[i][2]);
                acc[i][3] = fmaf(a, w.w, acc[i][3]);
            }
        }
    }

    float4 b = *((const float4*)bias + tx);
#pragma unroll
    for (int i = 0; i < 4; i++) {
        float4 v;
        v.x = acc[i][0] + b.x;
        v.y = acc[i][1] + b.y;
        v.z = acc[i][2] + b.z;
        v.w = acc[i][3] + b.w;
        if (SILU) {
            v.x = silu_f(v.x); v.y = silu_f(v.y);
            v.z = silu_f(v.z); v.w = silu_f(v.w);
        }
        *(float4*)&sOut[(e0 + i) * outStride + tx * 4] = v;
    }
}

// SMEM layout sizes (floats)
#define SM_IN    (BE * IN_STRIDE)        // 16896
#define SM_W     (16 * 33 * 4)           // 2112
#define SM_HID   (BE * HID_STRIDE)       // 8448
#define SM_EF    (BE * HID_STRIDE)       // 8448
#define SMEM_EDGE_FLOATS (SM_IN + SM_W + SM_HID + SM_EF + BE*4 + BE + 128 + BE + BE)
#define SMEM_EDGE_BYTES  (SMEM_EDGE_FLOATS * 4)
#define SMEM_NODE_FLOATS (SM_IN + SM_W + SM_HID)
#define SMEM_NODE_BYTES  (SMEM_NODE_FLOATS * 4)

__global__ void __launch_bounds__(THREADS, 1)
zero_kernel()
{
    int i = blockIdx.x * blockDim.x + threadIdx.x;
    int st = gridDim.x * blockDim.x;
    for (int k = i; k < N_NODES * HDIM; k += st) g_hagg[k] = 0.0f;
    for (int k = i; k < N_NODES * 3;    k += st) g_cagg[k] = 0.0f;
    for (int k = i; k < N_NODES;        k += st) g_cnt[k]  = 0.0f;
}

__global__ void __launch_bounds__(THREADS, 1)
edge_kernel(const float* __restrict__ h, const float* __restrict__ y,
            const int* __restrict__ ei,
            const float* __restrict__ We1, const float* __restrict__ be1,
            const float* __restrict__ We2, const float* __restrict__ be2,
            const float* __restrict__ Wc1, const float* __restrict__ bc1,
            const float* __restrict__ Wc2)
{
    extern __shared__ float sm[];
    float* s_in     = sm;
    float* s_w      = s_in + SM_IN;
    float* s_hid    = s_w + SM_W;
    float* s_ef     = s_hid + SM_HID;
    float* s_diff   = s_ef + SM_EF;        // [BE][4]
    float* s_scalar = s_diff + BE * 4;     // [BE]
    float* s_wc2    = s_scalar + BE;       // [128]
    int*   s_row    = (int*)(s_wc2 + 128); // [BE]
    int*   s_col    = s_row + BE;          // [BE]

    const int tid  = threadIdx.x;
    const int lane = tid & 31;
    const int wid  = tid >> 5;
    const int e0g  = blockIdx.x * BE;

    if (tid < BE) {
        int r = ei[e0g + tid];
        int c = ei[N_EDGES + e0g + tid];
        s_row[tid] = r;
        s_col[tid] = c;
        float dx = y[r * 3 + 0] - y[c * 3 + 0];
        float dy = y[r * 3 + 1] - y[c * 3 + 1];
        float dz = y[r * 3 + 2] - y[c * 3 + 2];
        s_diff[tid * 4 + 0] = dx;
        s_diff[tid * 4 + 1] = dy;
        s_diff[tid * 4 + 2] = dz;
        s_in[tid * IN_STRIDE + 256] = dx * dx + dy * dy + dz * dz;
    }
    if (tid < 128) s_wc2[tid] = Wc2[tid];
    __syncthreads();

    // Gather h[row], h[col] -> s_in[e][0:128], s_in[e][128:256]
    for (int t = wid; t < 2 * BE; t += 16) {
        int e = t >> 1, half = t & 1;
        int node = half ? s_col[e] : s_row[e];
        float4 v = *((const float4*)(h + (size_t)node * 128) + lane);
        *(float4*)&s_in[e * IN_STRIDE + half * 128 + lane * 4] = v;
    }
    // (gemm's leading __syncthreads covers the gather)

    gemm_tile<257, true>(s_in, IN_STRIDE, We1, be1, s_hid, HID_STRIDE, s_w);
    gemm_tile<128, true>(s_hid, HID_STRIDE, We2, be2, s_ef, HID_STRIDE, s_w);
    // c1 overlays the (now dead) input tile region
    float* s_c1 = s_in;
    gemm_tile<128, true>(s_ef, HID_STRIDE, Wc1, bc1, s_c1, HID_STRIDE, s_w);
    __syncthreads();

    // GEMV: scalar[e] = c1[e] . Wc2   (warp wid handles edges wid*4..wid*4+3)
#pragma unroll
    for (int i = 0; i < 4; i++) {
        int e = wid * 4 + i;
        const float* c1 = s_c1 + e * HID_STRIDE;
        float p = c1[lane]      * s_wc2[lane]
                + c1[lane + 32] * s_wc2[lane + 32]
                + c1[lane + 64] * s_wc2[lane + 64]
                + c1[lane + 96] * s_wc2[lane + 96];
#pragma unroll
        for (int o = 16; o > 0; o >>= 1)
            p += __shfl_xor_sync(0xffffffffu, p, o);
        if (lane == 0) s_scalar[e] = p;
    }
    __syncthreads();

    // coord scatter + count
    if (tid < BE) {
        int r = s_row[tid];
        float s = s_scalar[tid];
        atomicAdd(&g_cagg[r * 3 + 0], s_diff[tid * 4 + 0] * s);
        atomicAdd(&g_cagg[r * 3 + 1], s_diff[tid * 4 + 1] * s);
        atomicAdd(&g_cagg[r * 3 + 2], s_diff[tid * 4 + 2] * s);
        atomicAdd(&g_cnt[r], 1.0f);
    }
    // edge_feat scatter
    for (int idx = tid; idx < BE * 128; idx += THREADS) {
        int e = idx >> 7, j = idx & 127;
        atomicAdd(&g_hagg[(size_t)s_row[e] * 128 + j], s_ef[e * HID_STRIDE + j]);
    }
}

__global__ void __launch_bounds__(THREADS, 1)
node_kernel(const float* __restrict__ h, const float* __restrict__ y,
            const float* __restrict__ Wn1, const float* __restrict__ bn1,
            const float* __restrict__ Wn2, const float* __restrict__ bn2,
            float* __restrict__ out_h, float* __restrict__ out_y)
{
    extern __shared__ float sm[];
    float* s_in  = sm;
    float* s_w   = s_in + SM_IN;
    float* s_hid = s_w + SM_W;

    const int tid  = threadIdx.x;
    const int lane = tid & 31;
    const int wid  = tid >> 5;
    const int n0   = blockIdx.x * BE;

    // Gather [h[n], g_hagg[n]] -> s_in[e][0:256]
    for (int t = wid; t < 2 * BE; t += 16) {
        int e = t >> 1, half = t & 1;
        int n = n0 + e;
        float4 v = make_float4(0.f, 0.f, 0.f, 0.f);
        if (n < N_NODES) {
            const float* src = half ? (g_hagg + (size_t)n * 128)
                                    : (h + (size_t)n * 128);
            v = *((const float4*)src + lane);
        }
        *(float4*)&s_in[e * IN_STRIDE + half * 128 + lane * 4] = v;
    }

    gemm_tile<256, true>(s_in, IN_STRIDE, Wn1, bn1, s_hid, HID_STRIDE, s_w);
    // output of second GEMM overlays the (dead) h_agg half of the input tile
    gemm_tile<128, false>(s_hid, HID_STRIDE, Wn2, bn2, s_in + 128, IN_STRIDE, s_w);
    __syncthreads();

    // residual + store h_out
    for (int idx = tid; idx < BE * 128; idx += THREADS) {
        int e = idx >> 7, j = idx & 127;
        int n = n0 + e;
        if (n < N_NODES)
            out_h[(size_t)n * 128 + j] = s_in[e * IN_STRIDE + j]
                                       + s_in[e * IN_STRIDE + 128 + j];
    }
    // y_out = y + agg / max(cnt, 1)
    if (tid < BE) {
        int n = n0 + tid;
        if (n < N_NODES) {
            float c = g_cnt[n];
            c = (c < 1.0f) ? 1.0f : c;
            out_y[n * 3 + 0] = y[n * 3 + 0] + g_cagg[n * 3 + 0] / c;
            out_y[n * 3 + 1] = y[n * 3 + 1] + g_cagg[n * 3 + 1] / c;
            out_y[n * 3 + 2] = y[n * 3 + 2] + g_cagg[n * 3 + 2] / c;
        }
    }
}

extern "C" void kernel_launch(void* const* d_in, const int* in_sizes, int n_in,
                              void* d_out, int out_size)
{
    const float* h   = (const float*)d_in[0];
    const float* y   = (const float*)d_in[1];
    const int*   ei  = (const int*)d_in[2];
    const float* We1 = (const float*)d_in[3];
    const float* be1 = (const float*)d_in[4];
    const float* We2 = (const float*)d_in[5];
    const float* be2 = (const float*)d_in[6];
    const float* Wc1 = (const float*)d_in[7];
    const float* bc1 = (const float*)d_in[8];
    const float* Wc2 = (const float*)d_in[9];
    const float* Wn1 = (const float*)d_in[10];
    const float* bn1 = (const float*)d_in[11];
    const float* Wn2 = (const float*)d_in[12];
    const float* bn2 = (const float*)d_in[13];

    float* out_h = (float*)d_out;
    float* out_y = out_h + (size_t)N_NODES * FDIM;

    cudaFuncSetAttribute(edge_kernel, cudaFuncAttributeMaxDynamicSharedMemorySize,
                         SMEM_EDGE_BYTES);
    cudaFuncSetAttribute(node_kernel, cudaFuncAttributeMaxDynamicSharedMemorySize,
                         SMEM_NODE_BYTES);

    zero_kernel<<<512, THREADS>>>();

    int edge_blocks = N_EDGES / BE;                 // 10000
    edge_kernel<<<edge_blocks, THREADS, SMEM_EDGE_BYTES>>>(
        h, y, ei, We1, be1, We2, be2, Wc1, bc1, Wc2);

    int node_blocks = (N_NODES + BE - 1) / BE;      // 157
    node_kernel<<<node_blocks, THREADS, SMEM_NODE_BYTES>>>(
        h, y, Wn1, bn1, Wn2, bn2, out_h, out_y);
}

// round 2
// speedup vs baseline: 1.0172x; 1.0172x over previous
#include <cuda_runtime.h>

#define N_NODES 10000
#define N_EDGES 640000

#define BE 64          // edges per block tile
#define TE 256         // edge kernel threads (8 warps)
#define TN 512         // node kernel threads
#define ES 66          // col-major activation tile stride (64 edges + 2 pad)

typedef unsigned long long u64;

// Scratch (device globals: no allocation allowed)
__device__ float g_hagg[N_NODES * 128];
__device__ float g_cagg[N_NODES * 3];
__device__ float g_cnt[N_NODES];

__device__ __forceinline__ float silu_f(float x) {
    return x / (1.0f + __expf(-x));
}

// ---------------- packed f32x2 primitives ----------------
__device__ __forceinline__ void fma2(u64 &d, u64 a, u64 b) {
    asm("fma.rn.f32x2 %0, %1, %2, %0;" : "+l"(d) : "l"(a), "l"(b));
}
__device__ __forceinline__ u64 dup2(float w) {
    u64 r; asm("mov.b64 %0, {%1, %1};" : "=l"(r) : "f"(w)); return r;
}
__device__ __forceinline__ void unpack2(u64 p, float &lo, float &hi) {
    asm("mov.b64 {%0, %1}, %2;" : "=f"(lo), "=f"(hi) : "l"(p));
}

// One k-step: acc[c][p] += a_pair[p] * (w_c, w_c)
// aRow: col-major activation row (this warp's 8 edges, 8B-aligned)
// wRow: 128 floats (one k row of W); lane owns cols {tx, tx+32, tx+64, tx+96}
__device__ __forceinline__ void kstep(const float* __restrict__ aRow,
                                      const float* __restrict__ wRow,
                                      int tx, u64 acc[4][4])
{
    u64 a0 = *(const u64*)(aRow + 0);
    u64 a1 = *(const u64*)(aRow + 2);
    u64 a2 = *(const u64*)(aRow + 4);
    u64 a3 = *(const u64*)(aRow + 6);
#pragma unroll
    for (int c = 0; c < 4; c++) {
        u64 w = dup2(wRow[tx + 32 * c]);
        fma2(acc[c][0], a0, w);
        fma2(acc[c][1], a1, w);
        fma2(acc[c][2], a2, w);
        fma2(acc[c][3], a3, w);
    }
}

// Epilogue: bias + (optional) silu, store col-major [c][e] (stride ES)
__device__ __forceinline__ void epilogue(u64 acc[4][4],
                                         const float* __restrict__ bias,
                                         float* __restrict__ sOut,
                                         int e0, int tx, bool do_silu)
{
#pragma unroll
    for (int c = 0; c < 4; c++) {
        int cg = tx + 32 * c;
        float b = bias[cg];
#pragma unroll
        for (int p = 0; p < 4; p++) {
            float lo, hi; unpack2(acc[c][p], lo, hi);
            lo += b; hi += b;
            if (do_silu) { lo = silu_f(lo); hi = silu_f(hi); }
            *(float2*)&sOut[cg * ES + e0 + 2 * p] = make_float2(lo, hi);
        }
    }
}

// GEMM, K=128, weights fully preloaded in SMEM [128][128]
__device__ __forceinline__ void gemm_pre128(const float* __restrict__ sIn,
                                            const float* __restrict__ sW,
                                            const float* __restrict__ bias,
                                            float* __restrict__ sOut,
                                            int e0, int tx, bool do_silu)
{
    u64 acc[4][4];
#pragma unroll
    for (int c = 0; c < 4; c++)
#pragma unroll
        for (int p = 0; p < 4; p++) acc[c][p] = 0ull;

#pragma unroll 8
    for (int k = 0; k < 128; k++)
        kstep(sIn + k * ES + e0, sW + k * 128, tx, acc);

    epilogue(acc, bias, sOut, e0, tx, do_silu);
}

// GEMM1, K=257, weights streamed L2->SMEM in 16-row chunks, double-buffered
__device__ __forceinline__ void gemm1_257(const float* __restrict__ sIn,
                                          const float* __restrict__ Wg,
                                          const float* __restrict__ bias,
                                          float* __restrict__ sOut,
                                          float* __restrict__ s_w,
                                          int e0, int tx, int tid, bool do_silu)
{
    u64 acc[4][4];
#pragma unroll
    for (int c = 0; c < 4; c++)
#pragma unroll
        for (int p = 0; p < 4; p++) acc[c][p] = 0ull;

    // chunk 0 -> buffer 0
    {
        const float* p = Wg + tid * 8;
        float4 v0 = *(const float4*)p;
        float4 v1 = *(const float4*)(p + 4);
        *(float4*)(s_w + tid * 8)     = v0;
        *(float4*)(s_w + tid * 8 + 4) = v1;
    }
    __syncthreads();   // also covers the gather into sIn

    int cb = 0;
#pragma unroll 1
    for (int ch = 0; ch < 16; ch++) {
        float4 n0, n1; float tv = 0.0f;
        if (ch < 15) {
            const float* p = Wg + (ch + 1) * 2048 + tid * 8;
            n0 = *(const float4*)p;
            n1 = *(const float4*)(p + 4);
        } else if (tid < 128) {
            tv = Wg[256 * 128 + tid];   // tail row k=256
        }

        const float* sW = s_w + cb * 2048;
        const float* aB = sIn + ch * 16 * ES + e0;
#pragma unroll
        for (int kk = 0; kk < 16; kk++)
            kstep(aB + kk * ES, sW + kk * 128, tx, acc);

        float* dst = s_w + (cb ^ 1) * 2048;
        if (ch < 15) {
            *(float4*)(dst + tid * 8)     = n0;
            *(float4*)(dst + tid * 8 + 4) = n1;
        } else if (tid < 128) {
            dst[tid] = tv;
        }
        __syncthreads();
        cb ^= 1;
    }
    // tail k = 256
    kstep(sIn + 256 * ES + e0, s_w + cb * 2048, tx, acc);

    epilogue(acc, bias, sOut, e0, tx, do_silu);
}

// ---------------- SMEM layout (edge kernel, floats) ----------------
// s_a    : 260*66 = 17160   (col-major input tile, K rows x 64 edges)
// s_w    : 2*2048 = 4096    (double-buffered W chunk for GEMM1)
// s_hid  : 128*66 = 8448
// s_ef   : 128*66 = 8448
// extras : diff 256, part 256, scalar 64, wc2 128, row/col 128 ints
#define SMEM_EDGE_FLOATS (17160 + 4096 + 8448 + 8448 + 256 + 256 + 64 + 128 + 128)
#define SMEM_EDGE_BYTES  (SMEM_EDGE_FLOATS * 4)

__global__ void __launch_bounds__(TE, 1)
zero_kernel()
{
    int i = blockIdx.x * blockDim.x + threadIdx.x;
    int st = gridDim.x * blockDim.x;
    for (int k = i; k < N_NODES * 128; k += st) g_hagg[k] = 0.0f;
    for (int k = i; k < N_NODES * 3;   k += st) g_cagg[k] = 0.0f;
    for (int k = i; k < N_NODES;       k += st) g_cnt[k]  = 0.0f;
}

__global__ void __launch_bounds__(TE, 1)
edge_kernel(const float* __restrict__ h, const float* __restrict__ y,
            const int* __restrict__ ei,
            const float* __restrict__ We1, const float* __restrict__ be1,
            const float* __restrict__ We2, const float* __restrict__ be2,
            const float* __restrict__ Wc1, const float* __restrict__ bc1,
            const float* __restrict__ Wc2)
{
    extern __shared__ float sm[];
    float* s_a      = sm;                  // [260][66] col-major
    float* s_w      = s_a + 17160;         // 2 x [16][128]
    float* s_hid    = s_w + 4096;          // [128][66]
    float* s_ef     = s_hid + 8448;        // [128][66]
    float* s_diff   = s_ef + 8448;         // [64][4]
    float* s_part   = s_diff + 256;        // [4][64]
    float* s_scalar = s_part + 256;        // [64]
    float* s_wc2    = s_scalar + 64;       // [128]
    int*   s_row    = (int*)(s_wc2 + 128); // [64]
    int*   s_col    = s_row + 64;          // [64]
    float* s_wbig   = s_a;                 // alias: 16384 <= 17160 floats
    float* s_c1     = s_hid;               // alias: GEMM3 output over dead s_hid

    const int tid  = threadIdx.x;
    const int lane = tid & 31;
    const int wid  = tid >> 5;
    const int tx   = lane;
    const int e0   = wid * 8;              // this warp's 8 edges
    const int e0g  = blockIdx.x * BE;

    if (tid < 64) {
        int r = ei[e0g + tid];
        int c = ei[N_EDGES + e0g + tid];
        s_row[tid] = r;
        s_col[tid] = c;
        float dx = y[r * 3 + 0] - y[c * 3 + 0];
        float dy = y[r * 3 + 1] - y[c * 3 + 1];
        float dz = y[r * 3 + 2] - y[c * 3 + 2];
        s_diff[tid * 4 + 0] = dx;
        s_diff[tid * 4 + 1] = dy;
        s_diff[tid * 4 + 2] = dz;
        s_a[256 * ES + tid] = dx * dx + dy * dy + dz * dz;   // radial row
    }
    if (tid < 128) s_wc2[tid] = Wc2[tid];
    __syncthreads();

    // Gather h[row], h[col] -> s_a col-major: s_a[k][e]
    for (int t = wid; t < 2 * BE; t += 8) {
        int e = t >> 1, half = t & 1;
        int node = half ? s_col[e] : s_row[e];
        const float* hp = h + (size_t)node * 128;
#pragma unroll
        for (int j = 0; j < 4; j++) {
            float v = hp[lane + 32 * j];
            s_a[(half * 128 + lane + 32 * j) * ES + e] = v;
        }
    }
    // (gemm1's first __syncthreads covers the gather)

    gemm1_257(s_a, We1, be1, s_hid, s_w, e0, tx, tid, true);
    __syncthreads();                       // all s_a reads done

    // Preload We2 (64KB) over dead s_a
#pragma unroll
    for (int i = 0; i < 16; i++)
        *(float4*)(s_wbig + i * 1024 + tid * 4) =
            *(const float4*)(We2 + i * 1024 + tid * 4);
    __syncthreads();
    gemm_pre128(s_hid, s_wbig, be2, s_ef, e0, tx, true);
    __syncthreads();

    // Preload Wc1 over the same region
#pragma unroll
    for (int i = 0; i < 16; i++)
        *(float4*)(s_wbig + i * 1024 + tid * 4) =
            *(const float4*)(Wc1 + i * 1024 + tid * 4);
    __syncthreads();
    gemm_pre128(s_ef, s_wbig, bc1, s_c1, e0, tx, true);
    __syncthreads();

    // GEMV: scalar[e] = c1[:,e] . Wc2  (c1 col-major)
    {
        int e = tid & 63, q = tid >> 6;
        float s = 0.0f;
#pragma unroll 8
        for (int c = q * 32; c < q * 32 + 32; c++)
            s += s_c1[c * ES + e] * s_wc2[c];
        s_part[q * 64 + e] = s;
    }
    __syncthreads();

    // coord scatter + count
    if (tid < 64) {
        float s = s_part[tid] + s_part[64 + tid] + s_part[128 + tid] + s_part[192 + tid];
        int r = s_row[tid];
        atomicAdd(&g_cagg[r * 3 + 0], s_diff[tid * 4 + 0] * s);
        atomicAdd(&g_cagg[r * 3 + 1], s_diff[tid * 4 + 1] * s);
        atomicAdd(&g_cagg[r * 3 + 2], s_diff[tid * 4 + 2] * s);
        atomicAdd(&g_cnt[r], 1.0f);
    }

    // edge_feat scatter (s_ef col-major: read [j][e], lanes sweep e -> conflict-free)
    for (int idx = tid; idx < BE * 128; idx += TE) {
        int e = idx & 63, j = idx >> 6;
        atomicAdd(&g_hagg[(size_t)s_row[e] * 128 + j], s_ef[j * ES + e]);
    }
}

// ================= node kernel (unchanged scalar path, ~1.5% of time) =========
#define IN_STRIDE 264
#define HID_STRIDE 132

template<int K, bool SILU>
__device__ __forceinline__ void gemm_tile(
    const float* __restrict__ sIn, int inStride,
    const float* __restrict__ W, const float* __restrict__ bias,
    float* __restrict__ sOut, int outStride,
    float* __restrict__ s_w)
{
    const int tx = threadIdx.x & 31;
    const int ty = threadIdx.x >> 5;   // 0..15
    const int r0 = ty * 4;

    float acc[4][4];
#pragma unroll
    for (int i = 0; i < 4; i++)
#pragma unroll
        for (int c = 0; c < 4; c++) acc[i][c] = 0.0f;

    constexpr int KFULL = (K / 16) * 16;

    for (int kc = 0; kc < KFULL; kc += 16) {
        __syncthreads();
        {
            int t = threadIdx.x;
            int r = t >> 5, c = t & 31;
            ((float4*)s_w)[r * 33 + c] =
                *((const float4*)(W + (size_t)(kc + r) * 128) + c);
        }
        __syncthreads();
#pragma unroll
        for (int kk = 0; kk < 16; kk += 4) {
            float4 av[4];
#pragma unroll
            for (int i = 0; i < 4; i++)
                av[i] = *(const float4*)&sIn[(r0 + i) * inStride + kc + kk];
#pragma unroll
            for (int q = 0; q < 4; q++) {
                float4 w = ((const float4*)s_w)[(kk + q) * 33 + tx];
#pragma unroll
                for (int i = 0; i < 4; i++) {
                    float a = (q == 0) ? av[i].x : (q == 1) ? av[i].y
                              : (q == 2) ? av[i].z : av[i].w;
                    acc[i][0] = fmaf(a, w.x, acc[i][0]);
                    acc[i][1] = fmaf(a, w.y, acc[i][1]);
                    acc[i][2] = fmaf(a, w.z, acc[i][2]);
                    acc[i][3] = fmaf(a, w.w, acc[i][3]);
                }
            }
        }
    }

    float4 b = *((const float4*)bias + tx);
#pragma unroll
    for (int i = 0; i < 4; i++) {
        float4 v;
        v.x = acc[i][0] + b.x;
        v.y = acc[i][1] + b.y;
        v.z = acc[i][2] + b.z;
        v.w = acc[i][3] + b.w;
        if (SILU) {
            v.x = silu_f(v.x); v.y = silu_f(v.y);
            v.z = silu_f(v.z); v.w = silu_f(v.w);
        }
        *(float4*)&sOut[(r0 + i) * outStride + tx * 4] = v;
    }
}

#define SM_IN    (BE * IN_STRIDE)
#define SM_W     (16 * 33 * 4)
#define SM_HID   (BE * HID_STRIDE)
#define SMEM_NODE_FLOATS (SM_IN + SM_W + SM_HID)
#define SMEM_NODE_BYTES  (SMEM_NODE_FLOATS * 4)

__global__ void __launch_bounds__(TN, 1)
node_kernel(const float* __restrict__ h, const float* __restrict__ y,
            const float* __restrict__ Wn1, const float* __restrict__ bn1,
            const float* __restrict__ Wn2, const float* __restrict__ bn2,
            float* __restrict__ out_h, float* __restrict__ out_y)
{
    extern __shared__ float sm[];
    float* s_in  = sm;
    float* s_w   = s_in + SM_IN;
    float* s_hid = s_w + SM_W;

    const int tid  = threadIdx.x;
    const int lane = tid & 31;
    const int wid  = tid >> 5;
    const int n0   = blockIdx.x * BE;

    for (int t = wid; t < 2 * BE; t += 16) {
        int e = t >> 1, half = t & 1;
        int n = n0 + e;
        float4 v = make_float4(0.f, 0.f, 0.f, 0.f);
        if (n < N_NODES) {
            const float* src = half ? (g_hagg + (size_t)n * 128)
                                    : (h + (size_t)n * 128);
            v = *((const float4*)src + lane);
        }
        *(float4*)&s_in[e * IN_STRIDE + half * 128 + lane * 4] = v;
    }

    gemm_tile<256, true>(s_in, IN_STRIDE, Wn1, bn1, s_hid, HID_STRIDE, s_w);
    gemm_tile<128, false>(s_hid, HID_STRIDE, Wn2, bn2, s_in + 128, IN_STRIDE, s_w);
    __syncthreads();

    for (int idx = tid; idx < BE * 128; idx += TN) {
        int e = idx >> 7, j = idx & 127;
        int n = n0 + e;
        if (n < N_NODES)
            out_h[(size_t)n * 128 + j] = s_in[e * IN_STRIDE + j]
                                       + s_in[e * IN_STRIDE + 128 + j];
    }
    if (tid < BE) {
        int n = n0 + tid;
        if (n < N_NODES) {
            float c = g_cnt[n];
            c = (c < 1.0f) ? 1.0f : c;
            out_y[n * 3 + 0] = y[n * 3 + 0] + g_cagg[n * 3 + 0] / c;
            out_y[n * 3 + 1] = y[n * 3 + 1] + g_cagg[n * 3 + 1] / c;
            out_y[n * 3 + 2] = y[n * 3 + 2] + g_cagg[n * 3 + 2] / c;
        }
    }
}

extern "C" void kernel_launch(void* const* d_in, const int* in_sizes, int n_in,
                              void* d_out, int out_size)
{
    const float* h   = (const float*)d_in[0];
    const float* y   = (const float*)d_in[1];
    const int*   ei  = (const int*)d_in[2];
    const float* We1 = (const float*)d_in[3];
    const float* be1 = (const float*)d_in[4];
    const float* We2 = (const float*)d_in[5];
    const float* be2 = (const float*)d_in[6];
    const float* Wc1 = (const float*)d_in[7];
    const float* bc1 = (const float*)d_in[8];
    const float* Wc2 = (const float*)d_in[9];
    const float* Wn1 = (const float*)d_in[10];
    const float* bn1 = (const float*)d_in[11];
    const float* Wn2 = (const float*)d_in[12];
    const float* bn2 = (const float*)d_in[13];

    float* out_h = (float*)d_out;
    float* out_y = out_h + (size_t)N_NODES * 128;

    cudaFuncSetAttribute(edge_kernel, cudaFuncAttributeMaxDynamicSharedMemorySize,
                         SMEM_EDGE_BYTES);
    cudaFuncSetAttribute(node_kernel, cudaFuncAttributeMaxDynamicSharedMemorySize,
                         SMEM_NODE_BYTES);

    zero_kernel<<<512, TE>>>();

    edge_kernel<<<N_EDGES / BE, TE, SMEM_EDGE_BYTES>>>(
        h, y, ei, We1, be1, We2, be2, Wc1, bc1, Wc2);

    node_kernel<<<(N_NODES + BE - 1) / BE, TN, SMEM_NODE_BYTES>>>(
        h, y, Wn1, bn1, Wn2, bn2, out_h, out_y);
}